// round 1
// baseline (speedup 1.0000x reference)
#include <cuda_runtime.h>

#define NN   50000
#define EE   800000
#define EDEC 100000
#define F1   128     // H1*HID
#define F2   256     // H2*HID

// ---------------- scratch (device globals: no allocation allowed) -------------
__device__ float g_h1[NN * F1];     // x @ W1
__device__ float g_z1[NN * F1];     // layer1 output (post relu+bias)
__device__ float g_h2[NN * F2];     // z1 @ W2
__device__ float g_z2[NN * F2];     // layer2 output
__device__ float g_als1[NN * 4];
__device__ float g_ald1[NN * 4];
__device__ float g_als2[NN * 8];
__device__ float g_ald2[NN * 8];
__device__ int   g_cnt[NN];
__device__ int   g_off[NN];
__device__ int   g_cur[NN];
__device__ int   g_csr[EE];

// ---------------- GEMM: C[n,M] = A[n,128] @ B[128,M] --------------------------
__global__ __launch_bounds__(256) void gemm128(const float* __restrict__ A,
                                               const float* __restrict__ B,
                                               float* __restrict__ C,
                                               int n, int M) {
    __shared__ float As[16][64];
    __shared__ float Bs[16][64];
    int tid = threadIdx.x;
    int tx = tid & 15, ty = tid >> 4;
    int rowBase = blockIdx.x * 64, colBase = blockIdx.y * 64;
    float acc[4][4] = {};
    int aRow = tid >> 2, aCol = (tid & 3) * 4;
    int bRow = tid >> 4, bCol = (tid & 15) * 4;

    for (int k0 = 0; k0 < 128; k0 += 16) {
        float4 av = make_float4(0.f, 0.f, 0.f, 0.f);
        int gr = rowBase + aRow;
        if (gr < n) av = *(const float4*)(A + (size_t)gr * 128 + k0 + aCol);
        As[aCol + 0][aRow] = av.x;
        As[aCol + 1][aRow] = av.y;
        As[aCol + 2][aRow] = av.z;
        As[aCol + 3][aRow] = av.w;
        *(float4*)(&Bs[bRow][bCol]) =
            *(const float4*)(B + (size_t)(k0 + bRow) * M + colBase + bCol);
        __syncthreads();
#pragma unroll
        for (int k = 0; k < 16; k++) {
            float4 a4 = *(const float4*)(&As[k][ty * 4]);
            float4 b4 = *(const float4*)(&Bs[k][tx * 4]);
            float a[4] = {a4.x, a4.y, a4.z, a4.w};
            float b[4] = {b4.x, b4.y, b4.z, b4.w};
#pragma unroll
            for (int i = 0; i < 4; i++)
#pragma unroll
                for (int j = 0; j < 4; j++) acc[i][j] += a[i] * b[j];
        }
        __syncthreads();
    }
#pragma unroll
    for (int i = 0; i < 4; i++) {
        int r = rowBase + ty * 4 + i;
        if (r < n)
            *(float4*)(C + (size_t)r * M + colBase + tx * 4) =
                make_float4(acc[i][0], acc[i][1], acc[i][2], acc[i][3]);
    }
}

// ------------- attention coefficients al_s/al_d per node -----------------------
template <int HEADS, int W>
__global__ void al_kernel(const float* __restrict__ h,
                          const float* __restrict__ a_s,
                          const float* __restrict__ a_d,
                          float* __restrict__ als, float* __restrict__ ald) {
    int warp = (blockIdx.x * blockDim.x + threadIdx.x) >> 5;
    int lane = threadIdx.x & 31;
    if (warp >= NN) return;
    const float* row = h + (size_t)warp * W;
#pragma unroll
    for (int hd = 0; hd < HEADS; hd++) {
        float v = row[hd * 32 + lane];
        float s = v * a_s[hd * 32 + lane];
        float d = v * a_d[hd * 32 + lane];
#pragma unroll
        for (int o = 16; o; o >>= 1) {
            s += __shfl_xor_sync(0xffffffffu, s, o);
            d += __shfl_xor_sync(0xffffffffu, d, o);
        }
        if (lane == 0) {
            als[warp * HEADS + hd] = s;
            ald[warp * HEADS + hd] = d;
        }
    }
}

// ---------------- CSR construction --------------------------------------------
__global__ void zero_kernel() {
    int i = blockIdx.x * blockDim.x + threadIdx.x;
    if (i < NN) { g_cnt[i] = 0; g_cur[i] = 0; }
}

__global__ void hist_kernel(const int* __restrict__ dst) {
    int e = blockIdx.x * blockDim.x + threadIdx.x;
    if (e < EE) atomicAdd(&g_cnt[dst[e]], 1);
}

__global__ void scan_kernel() {  // single block, 1024 threads
    __shared__ int sm[1024];
    __shared__ int carry;
    int tid = threadIdx.x;
    if (tid == 0) carry = 0;
    __syncthreads();
    for (int base = 0; base < NN; base += 1024) {
        int i = base + tid;
        int v = (i < NN) ? g_cnt[i] : 0;
        sm[tid] = v;
        __syncthreads();
        for (int o = 1; o < 1024; o <<= 1) {
            int t = (tid >= o) ? sm[tid - o] : 0;
            __syncthreads();
            sm[tid] += t;
            __syncthreads();
        }
        if (i < NN) g_off[i] = carry + sm[tid] - v;
        __syncthreads();
        if (tid == 1023) carry += sm[1023];
        __syncthreads();
    }
}

__global__ void scatter_kernel(const int* __restrict__ src,
                               const int* __restrict__ dst) {
    int e = blockIdx.x * blockDim.x + threadIdx.x;
    if (e < EE) {
        int d = dst[e];
        int p = g_off[d] + atomicAdd(&g_cur[d], 1);
        g_csr[p] = src[e];
    }
}

// ---------------- fused GAT aggregation: one warp per destination node ---------
// exp without max subtraction (softmax is shift-invariant; max is detached in
// the reference, logits are O(±5), so this is numerically safe at 1e-3).
template <int HEADS, int W, bool RELU>
__global__ __launch_bounds__(256) void agg_kernel(
    const float* __restrict__ h, const float* __restrict__ als,
    const float* __restrict__ ald, const float* __restrict__ bias,
    float* __restrict__ z) {
    constexpr int V = W / 32;  // floats per lane
    int node = (blockIdx.x * blockDim.x + threadIdx.x) >> 5;
    int lane = threadIdx.x & 31;
    if (node >= NN) return;
    int head = (lane * V) >> 5;  // lane owns V consecutive channels of one head
    float aldh = ald[node * HEADS + head];
    float acc[V] = {};
    float den = 0.f;

    auto doEdge = [&](int s) {
        float e = als[s * HEADS + head] + aldh;
        e = e > 0.f ? e : 0.2f * e;  // LeakyReLU(0.2)
        float ex = __expf(e);
        den += ex;
        const float4* p = (const float4*)(h + (size_t)s * W + lane * V);
#pragma unroll
        for (int q = 0; q < V / 4; q++) {
            float4 hv = p[q];
            acc[q * 4 + 0] += ex * hv.x;
            acc[q * 4 + 1] += ex * hv.y;
            acc[q * 4 + 2] += ex * hv.z;
            acc[q * 4 + 3] += ex * hv.w;
        }
    };

    doEdge(node);  // self loop (add_self_loops=True)

    int start = g_off[node], m = g_cnt[node];
    for (int j0 = 0; j0 < m; j0 += 32) {
        int myS = (j0 + lane < m) ? g_csr[start + j0 + lane] : 0;
        int lim = min(32, m - j0);
        for (int k = 0; k < lim; k++) {
            int s = __shfl_sync(0xffffffffu, myS, k);
            doEdge(s);
        }
    }

    float inv = 1.f / (den + 1e-16f);
#pragma unroll
    for (int q = 0; q < V / 4; q++) {
        float4 o;
        o.x = acc[q * 4 + 0] * inv + bias[lane * V + q * 4 + 0];
        o.y = acc[q * 4 + 1] * inv + bias[lane * V + q * 4 + 1];
        o.z = acc[q * 4 + 2] * inv + bias[lane * V + q * 4 + 2];
        o.w = acc[q * 4 + 3] * inv + bias[lane * V + q * 4 + 3];
        if (RELU) {
            o.x = fmaxf(o.x, 0.f);
            o.y = fmaxf(o.y, 0.f);
            o.z = fmaxf(o.z, 0.f);
            o.w = fmaxf(o.w, 0.f);
        }
        *(float4*)(z + (size_t)node * W + lane * V + q * 4) = o;
    }
}

// ---------------- decode: logits = sum(z2[a] * z2[b]) --------------------------
__global__ __launch_bounds__(256) void decode_kernel(
    const int* __restrict__ pos, const int* __restrict__ neg,
    float* __restrict__ out) {
    int idx = (blockIdx.x * blockDim.x + threadIdx.x) >> 5;
    int lane = threadIdx.x & 31;
    if (idx >= 2 * EDEC) return;
    int a, b;
    if (idx < EDEC) {
        a = pos[idx];
        b = pos[EDEC + idx];
    } else {
        int k = idx - EDEC;
        a = neg[k];
        b = neg[EDEC + k];
    }
    const float4* ra = (const float4*)(g_z2 + (size_t)a * F2);
    const float4* rb = (const float4*)(g_z2 + (size_t)b * F2);
    float4 x0 = ra[lane * 2], x1 = ra[lane * 2 + 1];
    float4 y0 = rb[lane * 2], y1 = rb[lane * 2 + 1];
    float s = x0.x * y0.x + x0.y * y0.y + x0.z * y0.z + x0.w * y0.w +
              x1.x * y1.x + x1.y * y1.y + x1.z * y1.z + x1.w * y1.w;
#pragma unroll
    for (int o = 16; o; o >>= 1) s += __shfl_xor_sync(0xffffffffu, s, o);
    if (lane == 0) out[idx] = s;
}

// ---------------- launch --------------------------------------------------------
extern "C" void kernel_launch(void* const* d_in, const int* in_sizes, int n_in,
                              void* d_out, int out_size) {
    const float* x   = (const float*)d_in[0];
    const int*   ei  = (const int*)d_in[1];
    const int*   pos = (const int*)d_in[2];
    const int*   neg = (const int*)d_in[3];
    const float* W1  = (const float*)d_in[4];
    const float* as1 = (const float*)d_in[5];
    const float* ad1 = (const float*)d_in[6];
    const float* b1  = (const float*)d_in[7];
    const float* W2  = (const float*)d_in[8];
    const float* as2 = (const float*)d_in[9];
    const float* ad2 = (const float*)d_in[10];
    const float* b2  = (const float*)d_in[11];
    float* out = (float*)d_out;

    float *h1p, *z1p, *h2p, *z2p, *als1p, *ald1p, *als2p, *ald2p;
    cudaGetSymbolAddress((void**)&h1p, g_h1);
    cudaGetSymbolAddress((void**)&z1p, g_z1);
    cudaGetSymbolAddress((void**)&h2p, g_h2);
    cudaGetSymbolAddress((void**)&z2p, g_z2);
    cudaGetSymbolAddress((void**)&als1p, g_als1);
    cudaGetSymbolAddress((void**)&ald1p, g_ald1);
    cudaGetSymbolAddress((void**)&als2p, g_als2);
    cudaGetSymbolAddress((void**)&ald2p, g_ald2);

    const int TB = 256;
    int nodeWarpBlocks = (NN * 32 + TB - 1) / TB;  // 6250
    int edgeBlocks = (EE + TB - 1) / TB;

    // CSR build (dst-grouped; same CSR serves both layers)
    zero_kernel<<<(NN + TB - 1) / TB, TB>>>();
    hist_kernel<<<edgeBlocks, TB>>>(ei + EE);
    scan_kernel<<<1, 1024>>>();
    scatter_kernel<<<edgeBlocks, TB>>>(ei, ei + EE);

    // Layer 1
    gemm128<<<dim3((NN + 63) / 64, F1 / 64), TB>>>(x, W1, h1p, NN, F1);
    al_kernel<4, F1><<<nodeWarpBlocks, TB>>>(h1p, as1, ad1, als1p, ald1p);
    agg_kernel<4, F1, true><<<nodeWarpBlocks, TB>>>(h1p, als1p, ald1p, b1, z1p);

    // Layer 2
    gemm128<<<dim3((NN + 63) / 64, F2 / 64), TB>>>(z1p, W2, h2p, NN, F2);
    al_kernel<8, F2><<<nodeWarpBlocks, TB>>>(h2p, as2, ad2, als2p, ald2p);
    agg_kernel<8, F2, false><<<nodeWarpBlocks, TB>>>(h2p, als2p, ald2p, b2, z2p);

    // Decode
    decode_kernel<<<(2 * EDEC * 32 + TB - 1) / TB, TB>>>(pos, neg, out);
}

// round 2
// speedup vs baseline: 1.1319x; 1.1319x over previous
#include <cuda_runtime.h>

#define NN   50000
#define EE   800000
#define EDEC 100000
#define F1   128     // H1*HID
#define F2   256     // H2*HID

// ---------------- scratch (device globals: no allocation allowed) -------------
__device__ float g_h1[NN * F1];     // x @ W1
__device__ float g_z1[NN * F1];     // layer1 output (post relu+bias)
__device__ float g_h2[NN * F2];     // z1 @ W2
__device__ float g_z2[NN * F2];     // layer2 output
__device__ float g_als1[NN * 4];
__device__ float g_ald1[NN * 4];
__device__ float g_als2[NN * 8];
__device__ float g_ald2[NN * 8];
__device__ int   g_cnt[NN];
__device__ int   g_off[NN];
__device__ int   g_cur[NN];
__device__ int   g_csr[EE];
__device__ int   g_total;

// ---------------- packed f32x2 helpers -----------------------------------------
__device__ __forceinline__ unsigned long long pack2(float x) {
    unsigned long long d;
    asm("mov.b64 %0, {%1, %1};" : "=l"(d) : "f"(x));
    return d;
}
__device__ __forceinline__ void fma2(unsigned long long& d,
                                     unsigned long long a,
                                     unsigned long long b) {
    asm("fma.rn.f32x2 %0, %1, %2, %0;" : "+l"(d) : "l"(a), "l"(b));
}

// ---------------- GEMM: C[n,M] = A[n,128] @ B[128,M], f32x2 FMA -----------------
// 128x128 block tile, 256 threads, 8x8 per-thread (packed as 8x4 f32x2),
// BK=16, double-buffered smem.
__global__ __launch_bounds__(256) void gemm2k(const float* __restrict__ A,
                                              const float* __restrict__ B,
                                              float* __restrict__ C,
                                              int n, int M) {
    __shared__ float As[2][16][128];   // As[buf][k][row] (transposed)
    __shared__ float Bs[2][16][128];   // Bs[buf][k][col]
    int tid = threadIdx.x;
    int tx = tid & 15, ty = tid >> 4;
    int rowBase = blockIdx.x * 128, colBase = blockIdx.y * 128;

    // loader indices
    int aRow = tid >> 1;           // 0..127
    int aK = (tid & 1) * 8;        // 0 or 8
    int bK = tid >> 4;             // 0..15
    int bCol = (tid & 15) * 8;

    unsigned long long acc[8][4] = {};
    float4 av[2], bv[2];

    auto loadG = [&](int k0) {
        int gr = rowBase + aRow;
        if (gr < n) {
            av[0] = *(const float4*)(A + (size_t)gr * 128 + k0 + aK);
            av[1] = *(const float4*)(A + (size_t)gr * 128 + k0 + aK + 4);
        } else {
            av[0] = av[1] = make_float4(0.f, 0.f, 0.f, 0.f);
        }
        bv[0] = *(const float4*)(B + (size_t)(k0 + bK) * M + colBase + bCol);
        bv[1] = *(const float4*)(B + (size_t)(k0 + bK) * M + colBase + bCol + 4);
    };
    auto storeS = [&](int buf) {
#pragma unroll
        for (int q = 0; q < 2; q++) {
            As[buf][aK + q * 4 + 0][aRow] = q ? av[1].x : av[0].x;
            As[buf][aK + q * 4 + 1][aRow] = q ? av[1].y : av[0].y;
            As[buf][aK + q * 4 + 2][aRow] = q ? av[1].z : av[0].z;
            As[buf][aK + q * 4 + 3][aRow] = q ? av[1].w : av[0].w;
        }
        *(float4*)(&Bs[buf][bK][bCol]) = bv[0];
        *(float4*)(&Bs[buf][bK][bCol + 4]) = bv[1];
    };

    loadG(0);
    storeS(0);
    __syncthreads();

    for (int s = 0; s < 8; s++) {
        int buf = s & 1;
        if (s < 7) loadG((s + 1) * 16);
#pragma unroll
        for (int k = 0; k < 16; k++) {
            float4 a0 = *(const float4*)(&As[buf][k][ty * 8]);
            float4 a1 = *(const float4*)(&As[buf][k][ty * 8 + 4]);
            const unsigned long long* bp =
                (const unsigned long long*)(&Bs[buf][k][tx * 8]);
            unsigned long long b0 = bp[0], b1 = bp[1], b2 = bp[2], b3 = bp[3];
            float ar[8] = {a0.x, a0.y, a0.z, a0.w, a1.x, a1.y, a1.z, a1.w};
#pragma unroll
            for (int i = 0; i < 8; i++) {
                unsigned long long a2 = pack2(ar[i]);
                fma2(acc[i][0], a2, b0);
                fma2(acc[i][1], a2, b1);
                fma2(acc[i][2], a2, b2);
                fma2(acc[i][3], a2, b3);
            }
        }
        if (s < 7) storeS(buf ^ 1);
        __syncthreads();
    }

#pragma unroll
    for (int i = 0; i < 8; i++) {
        int r = rowBase + ty * 8 + i;
        if (r < n) {
            float* cp = C + (size_t)r * M + colBase + tx * 8;
            *(ulonglong2*)(cp) = make_ulonglong2(acc[i][0], acc[i][1]);
            *(ulonglong2*)(cp + 4) = make_ulonglong2(acc[i][2], acc[i][3]);
        }
    }
}

// ------------- attention coefficients al_s/al_d per node -----------------------
template <int HEADS, int W>
__global__ void al_kernel(const float* __restrict__ h,
                          const float* __restrict__ a_s,
                          const float* __restrict__ a_d,
                          float* __restrict__ als, float* __restrict__ ald) {
    int warp = (blockIdx.x * blockDim.x + threadIdx.x) >> 5;
    int lane = threadIdx.x & 31;
    if (warp >= NN) return;
    const float* row = h + (size_t)warp * W;
#pragma unroll
    for (int hd = 0; hd < HEADS; hd++) {
        float v = row[hd * 32 + lane];
        float s = v * a_s[hd * 32 + lane];
        float d = v * a_d[hd * 32 + lane];
#pragma unroll
        for (int o = 16; o; o >>= 1) {
            s += __shfl_xor_sync(0xffffffffu, s, o);
            d += __shfl_xor_sync(0xffffffffu, d, o);
        }
        if (lane == 0) {
            als[warp * HEADS + hd] = s;
            ald[warp * HEADS + hd] = d;
        }
    }
}

// ---------------- CSR construction --------------------------------------------
__global__ void zero_kernel() {
    int i = blockIdx.x * blockDim.x + threadIdx.x;
    if (i < NN) { g_cnt[i] = 0; g_cur[i] = 0; }
    if (i == 0) g_total = 0;
}

__global__ void hist_kernel(const int* __restrict__ dst) {
    int e = blockIdx.x * blockDim.x + threadIdx.x;
    if (e < EE) atomicAdd(&g_cnt[dst[e]], 1);
}

// Segment allocator: CSR segments need only be contiguous per node, not
// ordered — warp-scan + one atomicAdd per warp replaces a global scan.
__global__ void alloc_kernel() {
    int i = blockIdx.x * blockDim.x + threadIdx.x;
    int lane = threadIdx.x & 31;
    int v = (i < NN) ? g_cnt[i] : 0;
    int s = v;
#pragma unroll
    for (int o = 1; o < 32; o <<= 1) {
        int t = __shfl_up_sync(0xffffffffu, s, o);
        if (lane >= o) s += t;
    }
    int total = __shfl_sync(0xffffffffu, s, 31);
    int base = 0;
    if (lane == 31) base = atomicAdd(&g_total, total);
    base = __shfl_sync(0xffffffffu, base, 31);
    if (i < NN) g_off[i] = base + s - v;
}

__global__ void scatter_kernel(const int* __restrict__ src,
                               const int* __restrict__ dst) {
    int e = blockIdx.x * blockDim.x + threadIdx.x;
    if (e < EE) {
        int d = dst[e];
        int p = g_off[d] + atomicAdd(&g_cur[d], 1);
        g_csr[p] = src[e];
    }
}

// ---------------- fused GAT aggregation: one warp per destination node ---------
// exp without max subtraction (softmax is shift-invariant; max is detached in
// the reference, logits are O(±5), so this is numerically safe at 1e-3).
template <int HEADS, int W, bool RELU>
__global__ __launch_bounds__(256) void agg_kernel(
    const float* __restrict__ h, const float* __restrict__ als,
    const float* __restrict__ ald, const float* __restrict__ bias,
    float* __restrict__ z) {
    constexpr int V = W / 32;  // floats per lane
    int node = (blockIdx.x * blockDim.x + threadIdx.x) >> 5;
    int lane = threadIdx.x & 31;
    if (node >= NN) return;
    int head = (lane * V) >> 5;  // lane owns V consecutive channels of one head
    float aldh = ald[node * HEADS + head];
    float acc[V] = {};
    float den = 0.f;

    auto doEdge = [&](int s) {
        float e = als[s * HEADS + head] + aldh;
        e = e > 0.f ? e : 0.2f * e;  // LeakyReLU(0.2)
        float ex = __expf(e);
        den += ex;
        const float4* p = (const float4*)(h + (size_t)s * W + lane * V);
#pragma unroll
        for (int q = 0; q < V / 4; q++) {
            float4 hv = p[q];
            acc[q * 4 + 0] += ex * hv.x;
            acc[q * 4 + 1] += ex * hv.y;
            acc[q * 4 + 2] += ex * hv.z;
            acc[q * 4 + 3] += ex * hv.w;
        }
    };

    doEdge(node);  // self loop (add_self_loops=True)

    int start = g_off[node], m = g_cnt[node];
    for (int j0 = 0; j0 < m; j0 += 32) {
        int myS = (j0 + lane < m) ? g_csr[start + j0 + lane] : 0;
        int lim = min(32, m - j0);
        for (int k = 0; k < lim; k++) {
            int s = __shfl_sync(0xffffffffu, myS, k);
            doEdge(s);
        }
    }

    float inv = 1.f / (den + 1e-16f);
#pragma unroll
    for (int q = 0; q < V / 4; q++) {
        float4 o;
        o.x = acc[q * 4 + 0] * inv + bias[lane * V + q * 4 + 0];
        o.y = acc[q * 4 + 1] * inv + bias[lane * V + q * 4 + 1];
        o.z = acc[q * 4 + 2] * inv + bias[lane * V + q * 4 + 2];
        o.w = acc[q * 4 + 3] * inv + bias[lane * V + q * 4 + 3];
        if (RELU) {
            o.x = fmaxf(o.x, 0.f);
            o.y = fmaxf(o.y, 0.f);
            o.z = fmaxf(o.z, 0.f);
            o.w = fmaxf(o.w, 0.f);
        }
        *(float4*)(z + (size_t)node * W + lane * V + q * 4) = o;
    }
}

// ---------------- decode: logits = sum(z2[a] * z2[b]) --------------------------
__global__ __launch_bounds__(256) void decode_kernel(
    const int* __restrict__ pos, const int* __restrict__ neg,
    float* __restrict__ out) {
    int idx = (blockIdx.x * blockDim.x + threadIdx.x) >> 5;
    int lane = threadIdx.x & 31;
    if (idx >= 2 * EDEC) return;
    int a, b;
    if (idx < EDEC) {
        a = pos[idx];
        b = pos[EDEC + idx];
    } else {
        int k = idx - EDEC;
        a = neg[k];
        b = neg[EDEC + k];
    }
    const float4* ra = (const float4*)(g_z2 + (size_t)a * F2);
    const float4* rb = (const float4*)(g_z2 + (size_t)b * F2);
    float4 x0 = ra[lane * 2], x1 = ra[lane * 2 + 1];
    float4 y0 = rb[lane * 2], y1 = rb[lane * 2 + 1];
    float s = x0.x * y0.x + x0.y * y0.y + x0.z * y0.z + x0.w * y0.w +
              x1.x * y1.x + x1.y * y1.y + x1.z * y1.z + x1.w * y1.w;
#pragma unroll
    for (int o = 16; o; o >>= 1) s += __shfl_xor_sync(0xffffffffu, s, o);
    if (lane == 0) out[idx] = s;
}

// ---------------- launch --------------------------------------------------------
extern "C" void kernel_launch(void* const* d_in, const int* in_sizes, int n_in,
                              void* d_out, int out_size) {
    const float* x   = (const float*)d_in[0];
    const int*   ei  = (const int*)d_in[1];
    const int*   pos = (const int*)d_in[2];
    const int*   neg = (const int*)d_in[3];
    const float* W1  = (const float*)d_in[4];
    const float* as1 = (const float*)d_in[5];
    const float* ad1 = (const float*)d_in[6];
    const float* b1  = (const float*)d_in[7];
    const float* W2  = (const float*)d_in[8];
    const float* as2 = (const float*)d_in[9];
    const float* ad2 = (const float*)d_in[10];
    const float* b2  = (const float*)d_in[11];
    float* out = (float*)d_out;

    float *h1p, *z1p, *h2p, *z2p, *als1p, *ald1p, *als2p, *ald2p;
    cudaGetSymbolAddress((void**)&h1p, g_h1);
    cudaGetSymbolAddress((void**)&z1p, g_z1);
    cudaGetSymbolAddress((void**)&h2p, g_h2);
    cudaGetSymbolAddress((void**)&z2p, g_z2);
    cudaGetSymbolAddress((void**)&als1p, g_als1);
    cudaGetSymbolAddress((void**)&ald1p, g_ald1);
    cudaGetSymbolAddress((void**)&als2p, g_als2);
    cudaGetSymbolAddress((void**)&ald2p, g_ald2);

    const int TB = 256;
    int nodeWarpBlocks = (NN * 32 + TB - 1) / TB;  // 6250
    int edgeBlocks = (EE + TB - 1) / TB;

    // CSR build (dst-grouped; same CSR serves both layers)
    zero_kernel<<<(NN + TB - 1) / TB, TB>>>();
    hist_kernel<<<edgeBlocks, TB>>>(ei + EE);
    alloc_kernel<<<(NN + TB - 1) / TB, TB>>>();
    scatter_kernel<<<edgeBlocks, TB>>>(ei, ei + EE);

    // Layer 1
    gemm2k<<<dim3((NN + 127) / 128, F1 / 128), TB>>>(x, W1, h1p, NN, F1);
    al_kernel<4, F1><<<nodeWarpBlocks, TB>>>(h1p, as1, ad1, als1p, ald1p);
    agg_kernel<4, F1, true><<<nodeWarpBlocks, TB>>>(h1p, als1p, ald1p, b1, z1p);

    // Layer 2
    gemm2k<<<dim3((NN + 127) / 128, F2 / 128), TB>>>(z1p, W2, h2p, NN, F2);
    al_kernel<8, F2><<<nodeWarpBlocks, TB>>>(h2p, as2, ad2, als2p, ald2p);
    agg_kernel<8, F2, false><<<nodeWarpBlocks, TB>>>(h2p, als2p, ald2p, b2, z2p);

    // Decode
    decode_kernel<<<(2 * EDEC * 32 + TB - 1) / TB, TB>>>(pos, neg, out);
}

// round 3
// speedup vs baseline: 1.1800x; 1.0425x over previous
#include <cuda_runtime.h>
#include <cuda_fp16.h>

#define NN   50000
#define EE   800000
#define EDEC 100000
#define F1   128     // H1*HID
#define F2   256     // H2*HID

// ---------------- scratch (device globals: no allocation allowed) -------------
__device__ __half g_h1[NN * F1];    // x @ W1   (fp16 gather table)
__device__ float  g_z1[NN * F1];    // layer1 output (post relu+bias)
__device__ __half g_h2[NN * F2];    // z1 @ W2  (fp16 gather table)
__device__ float  g_z2[NN * F2];    // layer2 output
__device__ float g_als1[NN * 4];
__device__ float g_ald1[NN * 4];
__device__ float g_als2[NN * 8];
__device__ float g_ald2[NN * 8];
__device__ int   g_cnt[NN];
__device__ int   g_off[NN];
__device__ int   g_cur[NN];
__device__ int   g_csr[EE];
__device__ int   g_total;

// ---------------- packed f32x2 helpers -----------------------------------------
__device__ __forceinline__ unsigned long long pack2(float x) {
    unsigned long long d;
    asm("mov.b64 %0, {%1, %1};" : "=l"(d) : "f"(x));
    return d;
}
__device__ __forceinline__ void fma2(unsigned long long& d,
                                     unsigned long long a,
                                     unsigned long long b) {
    asm("fma.rn.f32x2 %0, %1, %2, %0;" : "+l"(d) : "l"(a), "l"(b));
}
__device__ __forceinline__ float2 unpack2(unsigned long long d) {
    float2 f;
    asm("mov.b64 {%0, %1}, %2;" : "=f"(f.x), "=f"(f.y) : "l"(d));
    return f;
}

// ---------------- GEMM: Ch[n,M] = half(A[n,128] @ B[128,M]) --------------------
// 128x128 block tile, 256 threads, 8x8 per-thread (packed as 8x4 f32x2),
// BK=16, double-buffered smem, fp16 output.
__global__ __launch_bounds__(256) void gemm2k(const float* __restrict__ A,
                                              const float* __restrict__ B,
                                              __half* __restrict__ Ch,
                                              int n, int M) {
    __shared__ float As[2][16][128];   // As[buf][k][row] (transposed)
    __shared__ float Bs[2][16][128];   // Bs[buf][k][col]
    int tid = threadIdx.x;
    int tx = tid & 15, ty = tid >> 4;
    int rowBase = blockIdx.x * 128, colBase = blockIdx.y * 128;

    int aRow = tid >> 1;           // 0..127
    int aK = (tid & 1) * 8;        // 0 or 8
    int bK = tid >> 4;             // 0..15
    int bCol = (tid & 15) * 8;

    unsigned long long acc[8][4] = {};
    float4 av[2], bv[2];

    auto loadG = [&](int k0) {
        int gr = rowBase + aRow;
        if (gr < n) {
            av[0] = *(const float4*)(A + (size_t)gr * 128 + k0 + aK);
            av[1] = *(const float4*)(A + (size_t)gr * 128 + k0 + aK + 4);
        } else {
            av[0] = av[1] = make_float4(0.f, 0.f, 0.f, 0.f);
        }
        bv[0] = *(const float4*)(B + (size_t)(k0 + bK) * M + colBase + bCol);
        bv[1] = *(const float4*)(B + (size_t)(k0 + bK) * M + colBase + bCol + 4);
    };
    auto storeS = [&](int buf) {
#pragma unroll
        for (int q = 0; q < 2; q++) {
            As[buf][aK + q * 4 + 0][aRow] = q ? av[1].x : av[0].x;
            As[buf][aK + q * 4 + 1][aRow] = q ? av[1].y : av[0].y;
            As[buf][aK + q * 4 + 2][aRow] = q ? av[1].z : av[0].z;
            As[buf][aK + q * 4 + 3][aRow] = q ? av[1].w : av[0].w;
        }
        *(float4*)(&Bs[buf][bK][bCol]) = bv[0];
        *(float4*)(&Bs[buf][bK][bCol + 4]) = bv[1];
    };

    loadG(0);
    storeS(0);
    __syncthreads();

    for (int s = 0; s < 8; s++) {
        int buf = s & 1;
        if (s < 7) loadG((s + 1) * 16);
#pragma unroll
        for (int k = 0; k < 16; k++) {
            float4 a0 = *(const float4*)(&As[buf][k][ty * 8]);
            float4 a1 = *(const float4*)(&As[buf][k][ty * 8 + 4]);
            const unsigned long long* bp =
                (const unsigned long long*)(&Bs[buf][k][tx * 8]);
            unsigned long long b0 = bp[0], b1 = bp[1], b2 = bp[2], b3 = bp[3];
            float ar[8] = {a0.x, a0.y, a0.z, a0.w, a1.x, a1.y, a1.z, a1.w};
#pragma unroll
            for (int i = 0; i < 8; i++) {
                unsigned long long a2 = pack2(ar[i]);
                fma2(acc[i][0], a2, b0);
                fma2(acc[i][1], a2, b1);
                fma2(acc[i][2], a2, b2);
                fma2(acc[i][3], a2, b3);
            }
        }
        if (s < 7) storeS(buf ^ 1);
        __syncthreads();
    }

#pragma unroll
    for (int i = 0; i < 8; i++) {
        int r = rowBase + ty * 8 + i;
        if (r < n) {
            __half2 hh[4];
#pragma unroll
            for (int j = 0; j < 4; j++) {
                float2 f = unpack2(acc[i][j]);
                hh[j] = __floats2half2_rn(f.x, f.y);
            }
            *(uint4*)(Ch + (size_t)r * M + colBase + tx * 8) = *(uint4*)hh;
        }
    }
}

// ------------- attention coefficients al_s/al_d per node -----------------------
template <int HEADS, int W>
__global__ void al_kernel(const __half* __restrict__ h,
                          const float* __restrict__ a_s,
                          const float* __restrict__ a_d,
                          float* __restrict__ als, float* __restrict__ ald) {
    int warp = (blockIdx.x * blockDim.x + threadIdx.x) >> 5;
    int lane = threadIdx.x & 31;
    if (warp >= NN) return;
    const __half* row = h + (size_t)warp * W;
#pragma unroll
    for (int hd = 0; hd < HEADS; hd++) {
        float v = __half2float(row[hd * 32 + lane]);
        float s = v * a_s[hd * 32 + lane];
        float d = v * a_d[hd * 32 + lane];
#pragma unroll
        for (int o = 16; o; o >>= 1) {
            s += __shfl_xor_sync(0xffffffffu, s, o);
            d += __shfl_xor_sync(0xffffffffu, d, o);
        }
        if (lane == 0) {
            als[warp * HEADS + hd] = s;
            ald[warp * HEADS + hd] = d;
        }
    }
}

// ---------------- CSR construction --------------------------------------------
__global__ void zero_kernel() {
    int i = blockIdx.x * blockDim.x + threadIdx.x;
    if (i < NN) { g_cnt[i] = 0; g_cur[i] = 0; }
    if (i == 0) g_total = 0;
}

__global__ void hist_kernel(const int* __restrict__ dst) {
    int e = blockIdx.x * blockDim.x + threadIdx.x;
    if (e < EE) atomicAdd(&g_cnt[dst[e]], 1);
}

// Segment allocator: CSR segments need only be contiguous per node, not
// ordered — warp-scan + one atomicAdd per warp replaces a global scan.
__global__ void alloc_kernel() {
    int i = blockIdx.x * blockDim.x + threadIdx.x;
    int lane = threadIdx.x & 31;
    int v = (i < NN) ? g_cnt[i] : 0;
    int s = v;
#pragma unroll
    for (int o = 1; o < 32; o <<= 1) {
        int t = __shfl_up_sync(0xffffffffu, s, o);
        if (lane >= o) s += t;
    }
    int total = __shfl_sync(0xffffffffu, s, 31);
    int base = 0;
    if (lane == 31) base = atomicAdd(&g_total, total);
    base = __shfl_sync(0xffffffffu, base, 31);
    if (i < NN) g_off[i] = base + s - v;
}

__global__ void scatter_kernel(const int* __restrict__ src,
                               const int* __restrict__ dst) {
    int e = blockIdx.x * blockDim.x + threadIdx.x;
    if (e < EE) {
        int d = dst[e];
        int p = g_off[d] + atomicAdd(&g_cur[d], 1);
        g_csr[p] = src[e];
    }
}

// ---------------- fused GAT aggregation: one warp per destination node ---------
// exp without max subtraction (softmax is shift-invariant; max is detached in
// the reference, logits are O(±5), so this is numerically safe at 1e-3).
// Features gathered in fp16, accumulated in fp32.
template <int HEADS, int W, bool RELU>
__global__ __launch_bounds__(256) void agg_kernel(
    const __half* __restrict__ h, const float* __restrict__ als,
    const float* __restrict__ ald, const float* __restrict__ bias,
    float* __restrict__ z) {
    constexpr int V = W / 32;  // floats per lane (4 or 8)
    int node = (blockIdx.x * blockDim.x + threadIdx.x) >> 5;
    int lane = threadIdx.x & 31;
    if (node >= NN) return;
    int head = (lane * V) >> 5;  // lane owns V consecutive channels of one head
    float aldh = ald[node * HEADS + head];
    float acc[V] = {};
    float den = 0.f;

    auto doEdge = [&](int s) {
        float e = als[s * HEADS + head] + aldh;
        e = e > 0.f ? e : 0.2f * e;  // LeakyReLU(0.2)
        float ex = __expf(e);
        den += ex;
        const __half2* p = (const __half2*)(h + (size_t)s * W + lane * V);
#pragma unroll
        for (int q = 0; q < V / 2; q++) {
            float2 f = __half22float2(p[q]);
            acc[q * 2 + 0] += ex * f.x;
            acc[q * 2 + 1] += ex * f.y;
        }
    };

    doEdge(node);  // self loop (add_self_loops=True)

    int start = g_off[node], m = g_cnt[node];
    for (int j0 = 0; j0 < m; j0 += 32) {
        int myS = (j0 + lane < m) ? g_csr[start + j0 + lane] : 0;
        int lim = min(32, m - j0);
        for (int k = 0; k < lim; k++) {
            int s = __shfl_sync(0xffffffffu, myS, k);
            doEdge(s);
        }
    }

    float inv = 1.f / (den + 1e-16f);
#pragma unroll
    for (int q = 0; q < V / 4; q++) {
        float4 o;
        o.x = acc[q * 4 + 0] * inv + bias[lane * V + q * 4 + 0];
        o.y = acc[q * 4 + 1] * inv + bias[lane * V + q * 4 + 1];
        o.z = acc[q * 4 + 2] * inv + bias[lane * V + q * 4 + 2];
        o.w = acc[q * 4 + 3] * inv + bias[lane * V + q * 4 + 3];
        if (RELU) {
            o.x = fmaxf(o.x, 0.f);
            o.y = fmaxf(o.y, 0.f);
            o.z = fmaxf(o.z, 0.f);
            o.w = fmaxf(o.w, 0.f);
        }
        *(float4*)(z + (size_t)node * W + lane * V + q * 4) = o;
    }
}

// ---------------- decode: logits = sum(z2[a] * z2[b]) --------------------------
__global__ __launch_bounds__(256) void decode_kernel(
    const int* __restrict__ pos, const int* __restrict__ neg,
    float* __restrict__ out) {
    int idx = (blockIdx.x * blockDim.x + threadIdx.x) >> 5;
    int lane = threadIdx.x & 31;
    if (idx >= 2 * EDEC) return;
    int a, b;
    if (idx < EDEC) {
        a = pos[idx];
        b = pos[EDEC + idx];
    } else {
        int k = idx - EDEC;
        a = neg[k];
        b = neg[EDEC + k];
    }
    const float4* ra = (const float4*)(g_z2 + (size_t)a * F2);
    const float4* rb = (const float4*)(g_z2 + (size_t)b * F2);
    float4 x0 = ra[lane * 2], x1 = ra[lane * 2 + 1];
    float4 y0 = rb[lane * 2], y1 = rb[lane * 2 + 1];
    float s = x0.x * y0.x + x0.y * y0.y + x0.z * y0.z + x0.w * y0.w +
              x1.x * y1.x + x1.y * y1.y + x1.z * y1.z + x1.w * y1.w;
#pragma unroll
    for (int o = 16; o; o >>= 1) s += __shfl_xor_sync(0xffffffffu, s, o);
    if (lane == 0) out[idx] = s;
}

// ---------------- launch --------------------------------------------------------
extern "C" void kernel_launch(void* const* d_in, const int* in_sizes, int n_in,
                              void* d_out, int out_size) {
    const float* x   = (const float*)d_in[0];
    const int*   ei  = (const int*)d_in[1];
    const int*   pos = (const int*)d_in[2];
    const int*   neg = (const int*)d_in[3];
    const float* W1  = (const float*)d_in[4];
    const float* as1 = (const float*)d_in[5];
    const float* ad1 = (const float*)d_in[6];
    const float* b1  = (const float*)d_in[7];
    const float* W2  = (const float*)d_in[8];
    const float* as2 = (const float*)d_in[9];
    const float* ad2 = (const float*)d_in[10];
    const float* b2  = (const float*)d_in[11];
    float* out = (float*)d_out;

    __half *h1p, *h2p;
    float *z1p, *z2p, *als1p, *ald1p, *als2p, *ald2p;
    cudaGetSymbolAddress((void**)&h1p, g_h1);
    cudaGetSymbolAddress((void**)&z1p, g_z1);
    cudaGetSymbolAddress((void**)&h2p, g_h2);
    cudaGetSymbolAddress((void**)&z2p, g_z2);
    cudaGetSymbolAddress((void**)&als1p, g_als1);
    cudaGetSymbolAddress((void**)&ald1p, g_ald1);
    cudaGetSymbolAddress((void**)&als2p, g_als2);
    cudaGetSymbolAddress((void**)&ald2p, g_ald2);

    const int TB = 256;
    int nodeWarpBlocks = (NN * 32 + TB - 1) / TB;  // 6250
    int edgeBlocks = (EE + TB - 1) / TB;

    // CSR build (dst-grouped; same CSR serves both layers)
    zero_kernel<<<(NN + TB - 1) / TB, TB>>>();
    hist_kernel<<<edgeBlocks, TB>>>(ei + EE);
    alloc_kernel<<<(NN + TB - 1) / TB, TB>>>();
    scatter_kernel<<<edgeBlocks, TB>>>(ei, ei + EE);

    // Layer 1
    gemm2k<<<dim3((NN + 127) / 128, F1 / 128), TB>>>(x, W1, h1p, NN, F1);
    al_kernel<4, F1><<<nodeWarpBlocks, TB>>>(h1p, as1, ad1, als1p, ald1p);
    agg_kernel<4, F1, true><<<nodeWarpBlocks, TB>>>(h1p, als1p, ald1p, b1, z1p);

    // Layer 2
    gemm2k<<<dim3((NN + 127) / 128, F2 / 128), TB>>>(z1p, W2, h2p, NN, F2);
    al_kernel<8, F2><<<nodeWarpBlocks, TB>>>(h2p, as2, ad2, als2p, ald2p);
    agg_kernel<8, F2, false><<<nodeWarpBlocks, TB>>>(h2p, als2p, ald2p, b2, z2p);

    // Decode
    decode_kernel<<<(2 * EDEC * 32 + TB - 1) / TB, TB>>>(pos, neg, out);
}

// round 4
// speedup vs baseline: 1.5504x; 1.3138x over previous
#include <cuda_runtime.h>
#include <cuda_fp16.h>
#include <mma.h>
using namespace nvcuda;

#define NN   50000
#define EE   800000
#define EDEC 100000
#define F1   128     // H1*HID
#define F2   256     // H2*HID

// ---------------- scratch (device globals: no allocation allowed) -------------
__device__ __half g_x16[NN * F1];   // x in fp16 (gemm1 A)
__device__ __half g_w1h[F1 * F1];   // W1 fp16
__device__ __half g_w2h[F1 * F2];   // W2 fp16
__device__ __half g_h1[NN * F1];    // x @ W1   (fp16 gather table)
__device__ __half g_z1[NN * F1];    // layer1 output, fp16 (gemm2 A)
__device__ __half g_h2[NN * F2];    // z1 @ W2  (fp16 gather table)
__device__ float  g_z2[NN * F2];    // layer2 output (fp32 for decode)
__device__ float g_als1[NN * 4];
__device__ float g_ald1[NN * 4];
__device__ float g_als2[NN * 8];
__device__ float g_ald2[NN * 8];
__device__ int   g_cnt[NN];
__device__ int   g_off[NN];
__device__ int   g_cur[NN];
__device__ int   g_csr[EE];
__device__ int   g_total;

// ---------------- fp32 -> fp16 convert (n % 8 == 0) ----------------------------
__global__ void f2h_kernel(const float* __restrict__ in,
                           __half* __restrict__ out, int n) {
    int i = (blockIdx.x * blockDim.x + threadIdx.x) * 8;
    if (i >= n) return;
    float4 a = *(const float4*)(in + i);
    float4 b = *(const float4*)(in + i + 4);
    __half2 h[4] = {__floats2half2_rn(a.x, a.y), __floats2half2_rn(a.z, a.w),
                    __floats2half2_rn(b.x, b.y), __floats2half2_rn(b.z, b.w)};
    *(uint4*)(out + i) = *(uint4*)h;
}

// ---------------- GEMM via tensor cores: Ch[n,M] = A[n,128] @ B[128,M] ---------
// fp16 in, fp32 accumulate, fp16 out. Block tile 128x64, 8 warps, warp 32x32.
__global__ __launch_bounds__(256) void gemm_wmma(const __half* __restrict__ A,
                                                 const __half* __restrict__ B,
                                                 __half* __restrict__ C,
                                                 int n, int M) {
    __shared__ __align__(16) char smem_raw[36864];
    __half (*As)[40] = (__half(*)[40])smem_raw;                 // 128 x 32 (+pad)
    __half (*Bs)[72] = (__half(*)[72])(smem_raw + 128 * 40 * 2);  // 32 x 64 (+pad)

    int tid = threadIdx.x;
    int w = tid >> 5, lane = tid & 31;
    int wr = w >> 1, wc = w & 1;  // 4x2 warp grid -> warp tile 32x32
    int rowBase = blockIdx.x * 128, colBase = blockIdx.y * 64;

    wmma::fragment<wmma::accumulator, 16, 16, 16, float> acc[2][2];
#pragma unroll
    for (int i = 0; i < 2; i++)
#pragma unroll
        for (int j = 0; j < 2; j++) wmma::fill_fragment(acc[i][j], 0.f);

    for (int kt = 0; kt < 128; kt += 32) {
        // stage A: 128x32 halves = 512 uint4, 2 per thread
#pragma unroll
        for (int c = tid; c < 512; c += 256) {
            int r = c >> 2, q = c & 3;
            uint4 v = make_uint4(0, 0, 0, 0);
            if (rowBase + r < n)
                v = *(const uint4*)(A + (size_t)(rowBase + r) * 128 + kt + q * 8);
            *(uint4*)&As[r][q * 8] = v;
        }
        // stage B: 32x64 halves = 256 uint4, 1 per thread
        {
            int r = tid >> 3, q = tid & 7;
            *(uint4*)&Bs[r][q * 8] =
                *(const uint4*)(B + (size_t)(kt + r) * M + colBase + q * 8);
        }
        __syncthreads();
#pragma unroll
        for (int kk = 0; kk < 32; kk += 16) {
            wmma::fragment<wmma::matrix_a, 16, 16, 16, __half, wmma::row_major> af[2];
            wmma::fragment<wmma::matrix_b, 16, 16, 16, __half, wmma::row_major> bf[2];
#pragma unroll
            for (int i = 0; i < 2; i++)
                wmma::load_matrix_sync(af[i], &As[wr * 32 + i * 16][kk], 40);
#pragma unroll
            for (int j = 0; j < 2; j++)
                wmma::load_matrix_sync(bf[j], &Bs[kk][wc * 32 + j * 16], 72);
#pragma unroll
            for (int i = 0; i < 2; i++)
#pragma unroll
                for (int j = 0; j < 2; j++)
                    wmma::mma_sync(acc[i][j], af[i], bf[j], acc[i][j]);
        }
        __syncthreads();
    }

    // epilogue: per-warp 32x32 float staging in smem, convert to fp16, store
    float (*Cs)[36] = (float(*)[36])(smem_raw + (size_t)w * 32 * 36 * 4);
#pragma unroll
    for (int i = 0; i < 2; i++)
#pragma unroll
        for (int j = 0; j < 2; j++)
            wmma::store_matrix_sync(&Cs[i * 16][j * 16], acc[i][j], 36,
                                    wmma::mem_row_major);
    __syncwarp();
    int row = rowBase + wr * 32 + lane;
    if (row < n) {
        __half* cp = C + (size_t)row * M + colBase + wc * 32;
#pragma unroll
        for (int q = 0; q < 4; q++) {
            __half2 h[4];
#pragma unroll
            for (int t = 0; t < 4; t++)
                h[t] = __floats2half2_rn(Cs[lane][q * 8 + t * 2],
                                         Cs[lane][q * 8 + t * 2 + 1]);
            *(uint4*)(cp + q * 8) = *(uint4*)h;
        }
    }
}

// ------------- attention coefficients al_s/al_d per node -----------------------
template <int HEADS, int W>
__global__ void al_kernel(const __half* __restrict__ h,
                          const float* __restrict__ a_s,
                          const float* __restrict__ a_d,
                          float* __restrict__ als, float* __restrict__ ald) {
    int warp = (blockIdx.x * blockDim.x + threadIdx.x) >> 5;
    int lane = threadIdx.x & 31;
    if (warp >= NN) return;
    const __half* row = h + (size_t)warp * W;
#pragma unroll
    for (int hd = 0; hd < HEADS; hd++) {
        float v = __half2float(row[hd * 32 + lane]);
        float s = v * a_s[hd * 32 + lane];
        float d = v * a_d[hd * 32 + lane];
#pragma unroll
        for (int o = 16; o; o >>= 1) {
            s += __shfl_xor_sync(0xffffffffu, s, o);
            d += __shfl_xor_sync(0xffffffffu, d, o);
        }
        if (lane == 0) {
            als[warp * HEADS + hd] = s;
            ald[warp * HEADS + hd] = d;
        }
    }
}

// ---------------- CSR construction --------------------------------------------
__global__ void zero_kernel() {
    int i = blockIdx.x * blockDim.x + threadIdx.x;
    if (i < NN) { g_cnt[i] = 0; g_cur[i] = 0; }
    if (i == 0) g_total = 0;
}

__global__ void hist_kernel(const int* __restrict__ dst) {
    int e = blockIdx.x * blockDim.x + threadIdx.x;
    if (e < EE) atomicAdd(&g_cnt[dst[e]], 1);
}

// Segment allocator: CSR segments need only be contiguous per node, not
// ordered — warp-scan + one atomicAdd per warp replaces a global scan.
__global__ void alloc_kernel() {
    int i = blockIdx.x * blockDim.x + threadIdx.x;
    int lane = threadIdx.x & 31;
    int v = (i < NN) ? g_cnt[i] : 0;
    int s = v;
#pragma unroll
    for (int o = 1; o < 32; o <<= 1) {
        int t = __shfl_up_sync(0xffffffffu, s, o);
        if (lane >= o) s += t;
    }
    int total = __shfl_sync(0xffffffffu, s, 31);
    int base = 0;
    if (lane == 31) base = atomicAdd(&g_total, total);
    base = __shfl_sync(0xffffffffu, base, 31);
    if (i < NN) g_off[i] = base + s - v;
}

__global__ void scatter_kernel(const int* __restrict__ src,
                               const int* __restrict__ dst) {
    int e = blockIdx.x * blockDim.x + threadIdx.x;
    if (e < EE) {
        int d = dst[e];
        int p = g_off[d] + atomicAdd(&g_cur[d], 1);
        g_csr[p] = src[e];
    }
}

// ---------------- fused GAT aggregation: one warp per destination node ---------
// exp without max subtraction (softmax is shift-invariant; max is detached in
// the reference, logits are O(±5), so this is numerically safe at 1e-3).
// Features gathered in fp16, accumulated in fp32.
template <int HEADS, int W, bool RELU, bool OUT_HALF>
__global__ __launch_bounds__(256) void agg_kernel(
    const __half* __restrict__ h, const float* __restrict__ als,
    const float* __restrict__ ald, const float* __restrict__ bias,
    void* __restrict__ zout) {
    constexpr int V = W / 32;  // floats per lane (4 or 8)
    int node = (blockIdx.x * blockDim.x + threadIdx.x) >> 5;
    int lane = threadIdx.x & 31;
    if (node >= NN) return;
    int head = (lane * V) >> 5;  // lane owns V consecutive channels of one head
    float aldh = ald[node * HEADS + head];
    float acc[V] = {};
    float den = 0.f;

    auto doEdge = [&](int s) {
        float e = als[s * HEADS + head] + aldh;
        e = e > 0.f ? e : 0.2f * e;  // LeakyReLU(0.2)
        float ex = __expf(e);
        den += ex;
        const __half2* p = (const __half2*)(h + (size_t)s * W + lane * V);
#pragma unroll
        for (int q = 0; q < V / 2; q++) {
            float2 f = __half22float2(p[q]);
            acc[q * 2 + 0] += ex * f.x;
            acc[q * 2 + 1] += ex * f.y;
        }
    };

    doEdge(node);  // self loop (add_self_loops=True)

    int start = g_off[node], m = g_cnt[node];
    for (int j0 = 0; j0 < m; j0 += 32) {
        int myS = (j0 + lane < m) ? g_csr[start + j0 + lane] : 0;
        int lim = min(32, m - j0);
        for (int k = 0; k < lim; k++) {
            int s = __shfl_sync(0xffffffffu, myS, k);
            doEdge(s);
        }
    }

    float inv = 1.f / (den + 1e-16f);
#pragma unroll
    for (int q = 0; q < V / 4; q++) {
        float4 o;
        o.x = acc[q * 4 + 0] * inv + bias[lane * V + q * 4 + 0];
        o.y = acc[q * 4 + 1] * inv + bias[lane * V + q * 4 + 1];
        o.z = acc[q * 4 + 2] * inv + bias[lane * V + q * 4 + 2];
        o.w = acc[q * 4 + 3] * inv + bias[lane * V + q * 4 + 3];
        if (RELU) {
            o.x = fmaxf(o.x, 0.f);
            o.y = fmaxf(o.y, 0.f);
            o.z = fmaxf(o.z, 0.f);
            o.w = fmaxf(o.w, 0.f);
        }
        if (OUT_HALF) {
            __half2 h2[2] = {__floats2half2_rn(o.x, o.y),
                             __floats2half2_rn(o.z, o.w)};
            *(uint2*)((__half*)zout + (size_t)node * W + lane * V + q * 4) =
                *(uint2*)h2;
        } else {
            *(float4*)((float*)zout + (size_t)node * W + lane * V + q * 4) = o;
        }
    }
}

// ---------------- decode: logits = sum(z2[a] * z2[b]) --------------------------
__global__ __launch_bounds__(256) void decode_kernel(
    const int* __restrict__ pos, const int* __restrict__ neg,
    float* __restrict__ out) {
    int idx = (blockIdx.x * blockDim.x + threadIdx.x) >> 5;
    int lane = threadIdx.x & 31;
    if (idx >= 2 * EDEC) return;
    int a, b;
    if (idx < EDEC) {
        a = pos[idx];
        b = pos[EDEC + idx];
    } else {
        int k = idx - EDEC;
        a = neg[k];
        b = neg[EDEC + k];
    }
    const float4* ra = (const float4*)(g_z2 + (size_t)a * F2);
    const float4* rb = (const float4*)(g_z2 + (size_t)b * F2);
    float4 x0 = ra[lane * 2], x1 = ra[lane * 2 + 1];
    float4 y0 = rb[lane * 2], y1 = rb[lane * 2 + 1];
    float s = x0.x * y0.x + x0.y * y0.y + x0.z * y0.z + x0.w * y0.w +
              x1.x * y1.x + x1.y * y1.y + x1.z * y1.z + x1.w * y1.w;
#pragma unroll
    for (int o = 16; o; o >>= 1) s += __shfl_xor_sync(0xffffffffu, s, o);
    if (lane == 0) out[idx] = s;
}

// ---------------- launch --------------------------------------------------------
extern "C" void kernel_launch(void* const* d_in, const int* in_sizes, int n_in,
                              void* d_out, int out_size) {
    const float* x   = (const float*)d_in[0];
    const int*   ei  = (const int*)d_in[1];
    const int*   pos = (const int*)d_in[2];
    const int*   neg = (const int*)d_in[3];
    const float* W1  = (const float*)d_in[4];
    const float* as1 = (const float*)d_in[5];
    const float* ad1 = (const float*)d_in[6];
    const float* b1  = (const float*)d_in[7];
    const float* W2  = (const float*)d_in[8];
    const float* as2 = (const float*)d_in[9];
    const float* ad2 = (const float*)d_in[10];
    const float* b2  = (const float*)d_in[11];
    float* out = (float*)d_out;

    __half *x16p, *w1hp, *w2hp, *h1p, *z1p, *h2p;
    float *z2p, *als1p, *ald1p, *als2p, *ald2p;
    cudaGetSymbolAddress((void**)&x16p, g_x16);
    cudaGetSymbolAddress((void**)&w1hp, g_w1h);
    cudaGetSymbolAddress((void**)&w2hp, g_w2h);
    cudaGetSymbolAddress((void**)&h1p, g_h1);
    cudaGetSymbolAddress((void**)&z1p, g_z1);
    cudaGetSymbolAddress((void**)&h2p, g_h2);
    cudaGetSymbolAddress((void**)&z2p, g_z2);
    cudaGetSymbolAddress((void**)&als1p, g_als1);
    cudaGetSymbolAddress((void**)&ald1p, g_ald1);
    cudaGetSymbolAddress((void**)&als2p, g_als2);
    cudaGetSymbolAddress((void**)&ald2p, g_ald2);

    const int TB = 256;
    int nodeWarpBlocks = (NN * 32 + TB - 1) / TB;  // 6250
    int edgeBlocks = (EE + TB - 1) / TB;

    // fp16 conversions
    f2h_kernel<<<(NN * F1 / 8 + TB - 1) / TB, TB>>>(x, x16p, NN * F1);
    f2h_kernel<<<(F1 * F1 / 8 + TB - 1) / TB, TB>>>(W1, w1hp, F1 * F1);
    f2h_kernel<<<(F1 * F2 / 8 + TB - 1) / TB, TB>>>(W2, w2hp, F1 * F2);

    // CSR build (dst-grouped; same CSR serves both layers)
    zero_kernel<<<(NN + TB - 1) / TB, TB>>>();
    hist_kernel<<<edgeBlocks, TB>>>(ei + EE);
    alloc_kernel<<<(NN + TB - 1) / TB, TB>>>();
    scatter_kernel<<<edgeBlocks, TB>>>(ei, ei + EE);

    // Layer 1
    gemm_wmma<<<dim3((NN + 127) / 128, F1 / 64), TB>>>(x16p, w1hp, h1p, NN, F1);
    al_kernel<4, F1><<<nodeWarpBlocks, TB>>>(h1p, as1, ad1, als1p, ald1p);
    agg_kernel<4, F1, true, true><<<nodeWarpBlocks, TB>>>(h1p, als1p, ald1p, b1, z1p);

    // Layer 2
    gemm_wmma<<<dim3((NN + 127) / 128, F2 / 64), TB>>>(z1p, w2hp, h2p, NN, F2);
    al_kernel<8, F2><<<nodeWarpBlocks, TB>>>(h2p, as2, ad2, als2p, ald2p);
    agg_kernel<8, F2, false, false><<<nodeWarpBlocks, TB>>>(h2p, als2p, ald2p, b2, z2p);

    // Decode
    decode_kernel<<<(2 * EDEC * 32 + TB - 1) / TB, TB>>>(pos, neg, out);
}

// round 5
// speedup vs baseline: 2.0604x; 1.3290x over previous
#include <cuda_runtime.h>
#include <cuda_fp16.h>
#include <mma.h>
using namespace nvcuda;

#define NN   50000
#define EE   800000
#define EDEC 100000
#define F1   128     // H1*HID
#define F2   256     // H2*HID

// ---------------- scratch (device globals: no allocation allowed) -------------
__device__ __half g_x16[NN * F1];   // x in fp16 (gemm1 A)
__device__ __half g_w1h[F1 * F1];   // W1 fp16
__device__ __half g_w2h[F1 * F2];   // W2 fp16
__device__ __half g_h1[NN * F1];    // x @ W1   (fp16 gather table)
__device__ __half g_z1[NN * F1];    // layer1 output, fp16 (gemm2 A)
__device__ __half g_h2[NN * F2];    // z1 @ W2  (fp16 gather table)
__device__ __half g_z2[NN * F2];    // layer2 output, fp16 (decode table)
__device__ float g_als1[NN * 4];
__device__ float g_ald1[NN * 4];
__device__ float g_als2[NN * 8];
__device__ float g_ald2[NN * 8];
__device__ int   g_cnt[NN];
__device__ int   g_off[NN];
__device__ int   g_csr[EE];
__device__ int   g_total;

// ---------------- fp32 -> fp16 convert (n % 8 == 0) ----------------------------
__global__ void f2h_kernel(const float* __restrict__ in,
                           __half* __restrict__ out, int n) {
    int i = (blockIdx.x * blockDim.x + threadIdx.x) * 8;
    if (i >= n) return;
    float4 a = *(const float4*)(in + i);
    float4 b = *(const float4*)(in + i + 4);
    __half2 h[4] = {__floats2half2_rn(a.x, a.y), __floats2half2_rn(a.z, a.w),
                    __floats2half2_rn(b.x, b.y), __floats2half2_rn(b.z, b.w)};
    *(uint4*)(out + i) = *(uint4*)h;
}

// ---------------- GEMM via tensor cores + fused attention coefficients ---------
// Ch[n,M] = half(A[n,128] @ B[128,M]); als/ald[n,M/32] fused in epilogue.
// fp16 in, fp32 accumulate. Block tile 128x64, 8 warps, warp 32x32.
// Warp col-tile (32) == HID, so each lane's epilogue row is one head.
__global__ __launch_bounds__(256) void gemm_wmma(const __half* __restrict__ A,
                                                 const __half* __restrict__ B,
                                                 __half* __restrict__ C,
                                                 const float* __restrict__ a_s,
                                                 const float* __restrict__ a_d,
                                                 float* __restrict__ als,
                                                 float* __restrict__ ald,
                                                 int n, int M) {
    __shared__ __align__(16) char smem_raw[36864];
    __half (*As)[40] = (__half(*)[40])smem_raw;                   // 128 x 32 (+pad)
    __half (*Bs)[72] = (__half(*)[72])(smem_raw + 128 * 40 * 2);  // 32 x 64 (+pad)

    int tid = threadIdx.x;
    int w = tid >> 5, lane = tid & 31;
    int wr = w >> 1, wc = w & 1;  // 4x2 warp grid -> warp tile 32x32
    int rowBase = blockIdx.x * 128, colBase = blockIdx.y * 64;

    wmma::fragment<wmma::accumulator, 16, 16, 16, float> acc[2][2];
#pragma unroll
    for (int i = 0; i < 2; i++)
#pragma unroll
        for (int j = 0; j < 2; j++) wmma::fill_fragment(acc[i][j], 0.f);

    for (int kt = 0; kt < 128; kt += 32) {
        // stage A: 128x32 halves = 512 uint4, 2 per thread
#pragma unroll
        for (int c = tid; c < 512; c += 256) {
            int r = c >> 2, q = c & 3;
            uint4 v = make_uint4(0, 0, 0, 0);
            if (rowBase + r < n)
                v = *(const uint4*)(A + (size_t)(rowBase + r) * 128 + kt + q * 8);
            *(uint4*)&As[r][q * 8] = v;
        }
        // stage B: 32x64 halves = 256 uint4, 1 per thread
        {
            int r = tid >> 3, q = tid & 7;
            *(uint4*)&Bs[r][q * 8] =
                *(const uint4*)(B + (size_t)(kt + r) * M + colBase + q * 8);
        }
        __syncthreads();
#pragma unroll
        for (int kk = 0; kk < 32; kk += 16) {
            wmma::fragment<wmma::matrix_a, 16, 16, 16, __half, wmma::row_major> af[2];
            wmma::fragment<wmma::matrix_b, 16, 16, 16, __half, wmma::row_major> bf[2];
#pragma unroll
            for (int i = 0; i < 2; i++)
                wmma::load_matrix_sync(af[i], &As[wr * 32 + i * 16][kk], 40);
#pragma unroll
            for (int j = 0; j < 2; j++)
                wmma::load_matrix_sync(bf[j], &Bs[kk][wc * 32 + j * 16], 72);
#pragma unroll
            for (int i = 0; i < 2; i++)
#pragma unroll
                for (int j = 0; j < 2; j++)
                    wmma::mma_sync(acc[i][j], af[i], bf[j], acc[i][j]);
        }
        __syncthreads();
    }

    // epilogue: per-warp 32x32 float staging in smem, fp16 store + al dots
    float (*Cs)[36] = (float(*)[36])(smem_raw + (size_t)w * 32 * 36 * 4);
#pragma unroll
    for (int i = 0; i < 2; i++)
#pragma unroll
        for (int j = 0; j < 2; j++)
            wmma::store_matrix_sync(&Cs[i * 16][j * 16], acc[i][j], 36,
                                    wmma::mem_row_major);
    __syncwarp();
    int row = rowBase + wr * 32 + lane;
    if (row < n) {
        float vals[32];
#pragma unroll
        for (int q = 0; q < 8; q++)
            *(float4*)&vals[q * 4] = *(const float4*)&Cs[lane][q * 4];

        __half2 hh[16];
#pragma unroll
        for (int t = 0; t < 16; t++)
            hh[t] = __floats2half2_rn(vals[2 * t], vals[2 * t + 1]);
        __half* cp = C + (size_t)row * M + colBase + wc * 32;
        *(uint4*)(cp + 0)  = *(uint4*)&hh[0];
        *(uint4*)(cp + 8)  = *(uint4*)&hh[4];
        *(uint4*)(cp + 16) = *(uint4*)&hh[8];
        *(uint4*)(cp + 24) = *(uint4*)&hh[12];

        int head = (colBase + wc * 32) >> 5;
        const float* asv = a_s + head * 32;
        const float* adv = a_d + head * 32;
        float sv = 0.f, dv = 0.f;
#pragma unroll
        for (int c = 0; c < 32; c++) {
            sv = fmaf(vals[c], asv[c], sv);
            dv = fmaf(vals[c], adv[c], dv);
        }
        int heads = M >> 5;
        als[row * heads + head] = sv;
        ald[row * heads + head] = dv;
    }
}

// ---------------- CSR construction --------------------------------------------
__global__ void zero_kernel() {
    int i = blockIdx.x * blockDim.x + threadIdx.x;
    if (i < NN) g_cnt[i] = 0;
    if (i == 0) g_total = 0;
}

__global__ void hist_kernel(const int* __restrict__ dst) {
    int e = blockIdx.x * blockDim.x + threadIdx.x;
    if (e < EE) atomicAdd(&g_cnt[dst[e]], 1);
}

// Segment allocator: CSR segments need only be contiguous per node, not
// ordered — warp-scan + one atomicAdd per warp replaces a global scan.
__global__ void alloc_kernel() {
    int i = blockIdx.x * blockDim.x + threadIdx.x;
    int lane = threadIdx.x & 31;
    int v = (i < NN) ? g_cnt[i] : 0;
    int s = v;
#pragma unroll
    for (int o = 1; o < 32; o <<= 1) {
        int t = __shfl_up_sync(0xffffffffu, s, o);
        if (lane >= o) s += t;
    }
    int total = __shfl_sync(0xffffffffu, s, 31);
    int base = 0;
    if (lane == 31) base = atomicAdd(&g_total, total);
    base = __shfl_sync(0xffffffffu, base, 31);
    if (i < NN) g_off[i] = base + s - v;
}

// scatter bumps g_off directly; afterwards g_off[d] = segment END.
// Consumers recompute start = g_off[d] - g_cnt[d].
__global__ void scatter_kernel(const int* __restrict__ src,
                               const int* __restrict__ dst) {
    int e = blockIdx.x * blockDim.x + threadIdx.x;
    if (e < EE) {
        int d = dst[e];
        int p = atomicAdd(&g_off[d], 1);
        g_csr[p] = src[e];
    }
}

// ---------------- fused GAT aggregation: one warp per destination node ---------
// exp without max subtraction (softmax is shift-invariant; max is detached in
// the reference, logits are O(±5), so this is numerically safe at 1e-3).
// Features gathered in fp16 (single vector load), accumulated in fp32.
template <int HEADS, int W, bool RELU>
__global__ __launch_bounds__(256) void agg_kernel(
    const __half* __restrict__ h, const float* __restrict__ als,
    const float* __restrict__ ald, const float* __restrict__ bias,
    __half* __restrict__ zout) {
    constexpr int V = W / 32;  // channels per lane (4 or 8)
    int node = (blockIdx.x * blockDim.x + threadIdx.x) >> 5;
    int lane = threadIdx.x & 31;
    if (node >= NN) return;
    int head = (lane * V) >> 5;  // lane owns V consecutive channels of one head
    float aldh = ald[node * HEADS + head];
    float acc[V] = {};
    float den = 0.f;

    auto doEdge = [&](int s) {
        float e = als[s * HEADS + head] + aldh;
        e = e > 0.f ? e : 0.2f * e;  // LeakyReLU(0.2)
        float ex = __expf(e);
        den += ex;
        const __half* p = h + (size_t)s * W + lane * V;
        __half2 hv[V / 2];
        if (V == 8) {
            uint4 raw = *(const uint4*)p;
            *(uint4*)hv = raw;
        } else {
            uint2 raw = *(const uint2*)p;
            *(uint2*)hv = raw;
        }
#pragma unroll
        for (int q = 0; q < V / 2; q++) {
            float2 f = __half22float2(hv[q]);
            acc[q * 2 + 0] += ex * f.x;
            acc[q * 2 + 1] += ex * f.y;
        }
    };

    doEdge(node);  // self loop (add_self_loops=True)

    int m = g_cnt[node];
    int start = g_off[node] - m;  // g_off holds segment end post-scatter
    for (int j0 = 0; j0 < m; j0 += 32) {
        int myS = (j0 + lane < m) ? g_csr[start + j0 + lane] : 0;
        int lim = min(32, m - j0);
        for (int k = 0; k < lim; k++) {
            int s = __shfl_sync(0xffffffffu, myS, k);
            doEdge(s);
        }
    }

    float inv = 1.f / (den + 1e-16f);
    __half2 oh[V / 2];
#pragma unroll
    for (int q = 0; q < V / 2; q++) {
        float ox = acc[q * 2 + 0] * inv + bias[lane * V + q * 2 + 0];
        float oy = acc[q * 2 + 1] * inv + bias[lane * V + q * 2 + 1];
        if (RELU) {
            ox = fmaxf(ox, 0.f);
            oy = fmaxf(oy, 0.f);
        }
        oh[q] = __floats2half2_rn(ox, oy);
    }
    if (V == 8)
        *(uint4*)(zout + (size_t)node * W + lane * V) = *(uint4*)oh;
    else
        *(uint2*)(zout + (size_t)node * W + lane * V) = *(uint2*)oh;
}

// ---------------- decode: logits = sum(z2[a] * z2[b]), fp16 table --------------
__global__ __launch_bounds__(256) void decode_kernel(
    const int* __restrict__ pos, const int* __restrict__ neg,
    float* __restrict__ out) {
    int idx = (blockIdx.x * blockDim.x + threadIdx.x) >> 5;
    int lane = threadIdx.x & 31;
    if (idx >= 2 * EDEC) return;
    int a, b;
    if (idx < EDEC) {
        a = pos[idx];
        b = pos[EDEC + idx];
    } else {
        int k = idx - EDEC;
        a = neg[k];
        b = neg[EDEC + k];
    }
    uint4 ra = *(const uint4*)(g_z2 + (size_t)a * F2 + lane * 8);
    uint4 rb = *(const uint4*)(g_z2 + (size_t)b * F2 + lane * 8);
    __half2* ha = (__half2*)&ra;
    __half2* hb = (__half2*)&rb;
    float s = 0.f;
#pragma unroll
    for (int q = 0; q < 4; q++) {
        float2 fa = __half22float2(ha[q]);
        float2 fb = __half22float2(hb[q]);
        s = fmaf(fa.x, fb.x, s);
        s = fmaf(fa.y, fb.y, s);
    }
#pragma unroll
    for (int o = 16; o; o >>= 1) s += __shfl_xor_sync(0xffffffffu, s, o);
    if (lane == 0) out[idx] = s;
}

// ---------------- launch --------------------------------------------------------
extern "C" void kernel_launch(void* const* d_in, const int* in_sizes, int n_in,
                              void* d_out, int out_size) {
    const float* x   = (const float*)d_in[0];
    const int*   ei  = (const int*)d_in[1];
    const int*   pos = (const int*)d_in[2];
    const int*   neg = (const int*)d_in[3];
    const float* W1  = (const float*)d_in[4];
    const float* as1 = (const float*)d_in[5];
    const float* ad1 = (const float*)d_in[6];
    const float* b1  = (const float*)d_in[7];
    const float* W2  = (const float*)d_in[8];
    const float* as2 = (const float*)d_in[9];
    const float* ad2 = (const float*)d_in[10];
    const float* b2  = (const float*)d_in[11];
    float* out = (float*)d_out;

    __half *x16p, *w1hp, *w2hp, *h1p, *z1p, *h2p, *z2p;
    float *als1p, *ald1p, *als2p, *ald2p;
    cudaGetSymbolAddress((void**)&x16p, g_x16);
    cudaGetSymbolAddress((void**)&w1hp, g_w1h);
    cudaGetSymbolAddress((void**)&w2hp, g_w2h);
    cudaGetSymbolAddress((void**)&h1p, g_h1);
    cudaGetSymbolAddress((void**)&z1p, g_z1);
    cudaGetSymbolAddress((void**)&h2p, g_h2);
    cudaGetSymbolAddress((void**)&z2p, g_z2);
    cudaGetSymbolAddress((void**)&als1p, g_als1);
    cudaGetSymbolAddress((void**)&ald1p, g_ald1);
    cudaGetSymbolAddress((void**)&als2p, g_als2);
    cudaGetSymbolAddress((void**)&ald2p, g_ald2);

    const int TB = 256;
    int nodeWarpBlocks = (NN * 32 + TB - 1) / TB;  // 6250
    int edgeBlocks = (EE + TB - 1) / TB;

    // fp16 conversions
    f2h_kernel<<<(NN * F1 / 8 + TB - 1) / TB, TB>>>(x, x16p, NN * F1);
    f2h_kernel<<<(F1 * F1 / 8 + TB - 1) / TB, TB>>>(W1, w1hp, F1 * F1);
    f2h_kernel<<<(F1 * F2 / 8 + TB - 1) / TB, TB>>>(W2, w2hp, F1 * F2);

    // CSR build (dst-grouped; same CSR serves both layers)
    zero_kernel<<<(NN + TB - 1) / TB, TB>>>();
    hist_kernel<<<edgeBlocks, TB>>>(ei + EE);
    alloc_kernel<<<(NN + TB - 1) / TB, TB>>>();
    scatter_kernel<<<edgeBlocks, TB>>>(ei, ei + EE);

    // Layer 1 (al fused into gemm epilogue)
    gemm_wmma<<<dim3((NN + 127) / 128, F1 / 64), TB>>>(
        x16p, w1hp, h1p, as1, ad1, als1p, ald1p, NN, F1);
    agg_kernel<4, F1, true><<<nodeWarpBlocks, TB>>>(h1p, als1p, ald1p, b1, z1p);

    // Layer 2
    gemm_wmma<<<dim3((NN + 127) / 128, F2 / 64), TB>>>(
        z1p, w2hp, h2p, as2, ad2, als2p, ald2p, NN, F2);
    agg_kernel<8, F2, false><<<nodeWarpBlocks, TB>>>(h2p, als2p, ald2p, b2, z2p);

    // Decode
    decode_kernel<<<(2 * EDEC * 32 + TB - 1) / TB, TB>>>(pos, neg, out);
}